// round 1
// baseline (speedup 1.0000x reference)
#include <cuda_runtime.h>
#include <math.h>

// Problem constants (hardcoded; scalar inputs 2..5 confirm these)
#define Gn 512          // B*N graphs
#define Pn 128          // patches per graph
#define Dn 256          // model dim
#define En 1024         // edges
#define Hn 8            // heads
#define HDn 32          // head dim
#define DFn 1024        // ffn dim
#define Mn (Gn*Pn)      // 65536 rows

// ---------------- scratch (device globals; no allocation allowed) ----------
__device__ float g_h[(size_t)Mn*Dn];
__device__ float g_q[(size_t)Mn*Dn];
__device__ float g_k[(size_t)Mn*Dn];
__device__ float g_v[(size_t)Mn*Dn];
__device__ float g_o[(size_t)Mn*Dn];
__device__ float g_f[(size_t)Mn*DFn];
__device__ float g_A[Pn*Pn];
__device__ float g_deg[Pn];

// ---------------- graph build: dense normalized adjacency ------------------
__global__ void k_init(float* A, float* deg) {
    int i = blockIdx.x*blockDim.x + threadIdx.x;
    if (i < Pn*Pn) A[i] = 0.f;
    if (i < Pn) deg[i] = 1.f;   // self-loop contributes 1 to degree
}
__global__ void k_count(const int* __restrict__ ei, float* deg) {
    int e = blockIdx.x*blockDim.x + threadIdx.x;
    if (e < En) atomicAdd(&deg[ei[En + e]], 1.f);
}
__global__ void k_dinv(float* deg) {
    int p = threadIdx.x;
    deg[p] = rsqrtf(deg[p]);    // deg >= 1 always (self loops)
}
__global__ void k_fill(const int* __restrict__ ei, const float* __restrict__ dinv, float* A) {
    int e = blockIdx.x*blockDim.x + threadIdx.x;
    if (e < En) {
        int s = ei[e], d = ei[En + e];
        atomicAdd(&A[d*Pn + s], dinv[s]*dinv[d]);
    } else if (e < En + Pn) {
        int p = e - En;
        atomicAdd(&A[p*Pn + p], dinv[p]*dinv[p]);
    }
}

// ---------------- SGEMM: C[M,N] = A[M,K] @ B[K,N] (+bias, +relu) -----------
// 128x128 tile, BK=8, 256 threads, 8x8 micro-tile per thread.
// blockIdx.z = batch index with element strides strA/strB/strC.
template<bool BIAS, bool RELU>
__global__ void __launch_bounds__(256, 2)
sgemm128(const float* __restrict__ Ag, const float* __restrict__ Bg,
         const float* __restrict__ bias, float* __restrict__ Cg,
         int M, int N, int K,
         long long strA, long long strB, long long strC)
{
    const int BM = 128, BN = 128, BK = 8;
    __shared__ float As[BK][BM];
    __shared__ float Bs[BK][BN];

    const float* A = Ag + (long long)blockIdx.z * strA;
    const float* B = Bg + (long long)blockIdx.z * strB;
    float*       C = Cg + (long long)blockIdx.z * strC;

    int bm0 = blockIdx.y * BM;
    int bn0 = blockIdx.x * BN;
    int t  = threadIdx.x;
    int tx = t & 15, ty = t >> 4;

    int arow = t >> 1;          // 0..127
    int acol = (t & 1) * 4;     // 0 or 4
    int brow = t >> 5;          // 0..7
    int bcol = (t & 31) * 4;    // 0..124

    float acc[8][8];
    #pragma unroll
    for (int i = 0; i < 8; i++)
        #pragma unroll
        for (int j = 0; j < 8; j++) acc[i][j] = 0.f;

    for (int k0 = 0; k0 < K; k0 += BK) {
        float4 av = *reinterpret_cast<const float4*>(&A[(size_t)(bm0+arow)*K + k0 + acol]);
        float4 bv = *reinterpret_cast<const float4*>(&B[(size_t)(k0+brow)*N + bn0 + bcol]);
        As[acol+0][arow] = av.x;
        As[acol+1][arow] = av.y;
        As[acol+2][arow] = av.z;
        As[acol+3][arow] = av.w;
        *reinterpret_cast<float4*>(&Bs[brow][bcol]) = bv;
        __syncthreads();
        #pragma unroll
        for (int kk = 0; kk < BK; kk++) {
            float ar[8], br[8];
            #pragma unroll
            for (int i = 0; i < 8; i++) ar[i] = As[kk][ty*8 + i];
            #pragma unroll
            for (int j = 0; j < 8; j++) br[j] = Bs[kk][tx*8 + j];
            #pragma unroll
            for (int i = 0; i < 8; i++)
                #pragma unroll
                for (int j = 0; j < 8; j++)
                    acc[i][j] = fmaf(ar[i], br[j], acc[i][j]);
        }
        __syncthreads();
    }

    #pragma unroll
    for (int i = 0; i < 8; i++) {
        int row = bm0 + ty*8 + i;
        #pragma unroll
        for (int j = 0; j < 8; j += 4) {
            int col = bn0 + tx*8 + j;
            float4 v;
            v.x = acc[i][j+0]; v.y = acc[i][j+1]; v.z = acc[i][j+2]; v.w = acc[i][j+3];
            if (BIAS) {
                v.x += bias[col+0]; v.y += bias[col+1];
                v.z += bias[col+2]; v.w += bias[col+3];
            }
            if (RELU) {
                v.x = fmaxf(v.x, 0.f); v.y = fmaxf(v.y, 0.f);
                v.z = fmaxf(v.z, 0.f); v.w = fmaxf(v.w, 0.f);
            }
            *reinterpret_cast<float4*>(&C[(size_t)row*N + col]) = v;
        }
    }
}

// ---------------- attention: one CTA per (head, graph) ---------------------
// Q,K,V stored as [G,P,D] with head h at columns [h*32, h*32+32).
__global__ void __launch_bounds__(128)
attn_kernel(const float* __restrict__ q, const float* __restrict__ k,
            const float* __restrict__ v, float* __restrict__ o)
{
    int head = blockIdx.x;
    int g    = blockIdx.y;
    int tid  = threadIdx.x;   // query row index, 0..127

    __shared__ float Ks[Pn][HDn];
    __shared__ float Vs[Pn][HDn];

    size_t rowbase = ((size_t)g*Pn + tid)*Dn + head*HDn;
    #pragma unroll
    for (int j = 0; j < HDn/4; j++) {
        reinterpret_cast<float4*>(Ks[tid])[j] = reinterpret_cast<const float4*>(k + rowbase)[j];
        reinterpret_cast<float4*>(Vs[tid])[j] = reinterpret_cast<const float4*>(v + rowbase)[j];
    }
    float qr[HDn];
    #pragma unroll
    for (int j = 0; j < HDn/4; j++) {
        float4 t4 = reinterpret_cast<const float4*>(q + rowbase)[j];
        qr[4*j+0] = t4.x; qr[4*j+1] = t4.y; qr[4*j+2] = t4.z; qr[4*j+3] = t4.w;
    }
    __syncthreads();

    const float scale = 0.17677669529663687f;   // 1/sqrt(32)

    // pass 1: row max
    float m = -1e30f;
    for (int j = 0; j < Pn; j++) {
        float s = 0.f;
        #pragma unroll
        for (int d = 0; d < HDn; d++) s = fmaf(qr[d], Ks[j][d], s);
        m = fmaxf(m, s*scale);
    }
    // pass 2: exp-sum + AV accumulate
    float l = 0.f;
    float acc[HDn];
    #pragma unroll
    for (int d = 0; d < HDn; d++) acc[d] = 0.f;
    for (int j = 0; j < Pn; j++) {
        float s = 0.f;
        #pragma unroll
        for (int d = 0; d < HDn; d++) s = fmaf(qr[d], Ks[j][d], s);
        float e = __expf(s*scale - m);
        l += e;
        #pragma unroll
        for (int d = 0; d < HDn; d++) acc[d] = fmaf(e, Vs[j][d], acc[d]);
    }
    float inv = 1.f / l;
    #pragma unroll
    for (int j = 0; j < HDn/4; j++) {
        float4 t4;
        t4.x = acc[4*j+0]*inv; t4.y = acc[4*j+1]*inv;
        t4.z = acc[4*j+2]*inv; t4.w = acc[4*j+3]*inv;
        reinterpret_cast<float4*>(o + rowbase)[j] = t4;
    }
}

// ---------------- LayerNorm(x + t) * g + b ; one CTA per row ---------------
__global__ void __launch_bounds__(Dn)
ln_kernel(const float* __restrict__ x, const float* __restrict__ t,
          const float* __restrict__ gam, const float* __restrict__ bet,
          float* __restrict__ out)
{
    int row = blockIdx.x;
    int f   = threadIdx.x;
    size_t idx = (size_t)row*Dn + f;
    float v = x[idx] + t[idx];

    __shared__ float sh[8];
    int lane = f & 31, w = f >> 5;

    float s = v;
    #pragma unroll
    for (int off = 16; off > 0; off >>= 1) s += __shfl_xor_sync(0xffffffffu, s, off);
    if (lane == 0) sh[w] = s;
    __syncthreads();
    float mean = 0.f;
    #pragma unroll
    for (int i = 0; i < 8; i++) mean += sh[i];
    mean *= (1.f/Dn);

    float d  = v - mean;
    float s2 = d*d;
    #pragma unroll
    for (int off = 16; off > 0; off >>= 1) s2 += __shfl_xor_sync(0xffffffffu, s2, off);
    __syncthreads();                 // protect sh reuse
    if (lane == 0) sh[w] = s2;
    __syncthreads();
    float var = 0.f;
    #pragma unroll
    for (int i = 0; i < 8; i++) var += sh[i];
    var *= (1.f/Dn);

    float r = rsqrtf(var + 1e-5f);
    out[idx] = d*r*gam[f] + bet[f];
}

// ---------------------------------------------------------------------------
extern "C" void kernel_launch(void* const* d_in, const int* in_sizes, int n_in,
                              void* d_out, int out_size)
{
    const float* x    = (const float*)d_in[0];
    const int*   ei   = (const int*)  d_in[1];
    const float* c1W  = (const float*)d_in[6];
    const float* c1b  = (const float*)d_in[7];
    const float* c2W  = (const float*)d_in[8];
    const float* c2b  = (const float*)d_in[9];
    const float* WqA  = (const float*)d_in[10];
    const float* bqA  = (const float*)d_in[11];
    const float* WkA  = (const float*)d_in[12];
    const float* bkA  = (const float*)d_in[13];
    const float* WvA  = (const float*)d_in[14];
    const float* bvA  = (const float*)d_in[15];
    const float* WoA  = (const float*)d_in[16];
    const float* boA  = (const float*)d_in[17];
    const float* W1A  = (const float*)d_in[18];
    const float* b1A  = (const float*)d_in[19];
    const float* W2A  = (const float*)d_in[20];
    const float* b2A  = (const float*)d_in[21];
    const float* l1gA = (const float*)d_in[22];
    const float* l1bA = (const float*)d_in[23];
    const float* l2gA = (const float*)d_in[24];
    const float* l2bA = (const float*)d_in[25];
    float* out = (float*)d_out;

    float *h, *q, *k, *v, *o, *f, *A, *deg;
    cudaGetSymbolAddress((void**)&h,   g_h);
    cudaGetSymbolAddress((void**)&q,   g_q);
    cudaGetSymbolAddress((void**)&k,   g_k);
    cudaGetSymbolAddress((void**)&v,   g_v);
    cudaGetSymbolAddress((void**)&o,   g_o);
    cudaGetSymbolAddress((void**)&f,   g_f);
    cudaGetSymbolAddress((void**)&A,   g_A);
    cudaGetSymbolAddress((void**)&deg, g_deg);

    // --- build dense normalized adjacency  (Â = D^-1/2 (A+I) D^-1/2) ---
    k_init <<<(Pn*Pn + 255)/256, 256>>>(A, deg);
    k_count<<<(En + 255)/256,    256>>>(ei, deg);
    k_dinv <<<1, Pn>>>(deg);
    k_fill <<<(En + Pn + 255)/256, 256>>>(ei, deg, A);

    const long long GP = (long long)Pn * Dn;   // 32768, per-graph stride
    dim3 gProj(Dn/128,  Mn/128, 1);   // (2, 512)
    dim3 gAgg (Dn/128,  1,      Gn);  // (2, 1, 512) batched
    dim3 gF1  (DFn/128, Mn/128, 1);   // (8, 512)

    // --- GCN conv1: xw = x @ W1c ; h = relu(Â @ xw + b) ---
    sgemm128<false,false><<<gProj, 256>>>(x, c1W, nullptr, q, Mn, Dn, Dn, 0, 0, 0);
    sgemm128<true, true ><<<gAgg,  256>>>(A, q, c1b, h, Pn, Dn, Pn, 0, GP, GP);
    // --- GCN conv2 ---
    sgemm128<false,false><<<gProj, 256>>>(h, c2W, nullptr, q, Mn, Dn, Dn, 0, 0, 0);
    sgemm128<true, true ><<<gAgg,  256>>>(A, q, c2b, h, Pn, Dn, Pn, 0, GP, GP);

    // --- 2 transformer encoder layers (post-LN) ---
    for (int l = 0; l < 2; l++) {
        const float* Wq = WqA + (size_t)l*Dn*Dn;   const float* bq = bqA + (size_t)l*Dn;
        const float* Wk = WkA + (size_t)l*Dn*Dn;   const float* bk = bkA + (size_t)l*Dn;
        const float* Wv = WvA + (size_t)l*Dn*Dn;   const float* bv = bvA + (size_t)l*Dn;
        const float* Wo = WoA + (size_t)l*Dn*Dn;   const float* bo = boA + (size_t)l*Dn;
        const float* W1 = W1A + (size_t)l*Dn*DFn;  const float* b1 = b1A + (size_t)l*DFn;
        const float* W2 = W2A + (size_t)l*DFn*Dn;  const float* b2 = b2A + (size_t)l*Dn;
        const float* l1g = l1gA + (size_t)l*Dn;    const float* l1b = l1bA + (size_t)l*Dn;
        const float* l2g = l2gA + (size_t)l*Dn;    const float* l2b = l2bA + (size_t)l*Dn;

        sgemm128<true,false><<<gProj, 256>>>(h, Wq, bq, q, Mn, Dn, Dn, 0, 0, 0);
        sgemm128<true,false><<<gProj, 256>>>(h, Wk, bk, k, Mn, Dn, Dn, 0, 0, 0);
        sgemm128<true,false><<<gProj, 256>>>(h, Wv, bv, v, Mn, Dn, Dn, 0, 0, 0);

        attn_kernel<<<dim3(Hn, Gn), 128>>>(q, k, v, o);

        sgemm128<true,false><<<gProj, 256>>>(o, Wo, bo, k, Mn, Dn, Dn, 0, 0, 0); // k reused as tmp
        ln_kernel<<<Mn, Dn>>>(h, k, l1g, l1b, h);

        sgemm128<true,true ><<<gF1,  256>>>(h, W1, b1, f, Mn, DFn, Dn, 0, 0, 0);
        sgemm128<true,false><<<gProj, 256>>>(f, W2, b2, k, Mn, Dn, DFn, 0, 0, 0);

        float* dst = (l == 1) ? out : h;
        ln_kernel<<<Mn, Dn>>>(h, k, l2g, l2b, dst);
    }
}

// round 3
// speedup vs baseline: 1.5338x; 1.5338x over previous
#include <cuda_runtime.h>
#include <cuda_bf16.h>
#include <mma.h>
#include <math.h>
#include <stdint.h>

using namespace nvcuda;

// Problem constants
#define Gn 512
#define Pn 128
#define Dn 256
#define En 1024
#define Hn 8
#define HDn 32
#define DFn 1024
#define Mn (Gn*Pn)

// ---------------- scratch (device globals) ----------------
__device__ float g_h[(size_t)Mn*Dn];
__device__ float g_q[(size_t)Mn*Dn];
__device__ float g_k[(size_t)Mn*Dn];
__device__ float g_v[(size_t)Mn*Dn];
__device__ __nv_bfloat16 g_as1[(size_t)Mn*2*Dn];    // [M][2*256]  hi|lo
__device__ __nv_bfloat16 g_as2[(size_t)Mn*2*DFn];   // [M][2*1024] hi|lo

// packed weights: [N][3K] bf16 = hi | lo | hi
#define W3_CONV   (Dn*3*Dn)                  // 196608
#define W3_LAYER  (4*W3_CONV + 2*(DFn*3*Dn)) // 4*196608 + 2*786432
__device__ __nv_bfloat16 g_w3[2*W3_CONV + 2*W3_LAYER];

__device__ float g_degf[Pn];
__device__ float g_dinv[Pn];
__device__ int   g_rp[Pn+1];
__device__ int   g_cur[Pn];
__device__ int   g_ci[En+Pn];
__device__ float g_wv[En+Pn];

// ---------------- helpers ----------------
__device__ __forceinline__ uint32_t smem_u32(const void* p) {
    uint32_t a;
    asm("{ .reg .u64 t; cvta.to.shared.u64 t, %1; cvt.u32.u64 %0, t; }" : "=r"(a) : "l"(p));
    return a;
}
__device__ __forceinline__ void cp_async16(uint32_t dst, const void* src) {
    asm volatile("cp.async.cg.shared.global [%0], [%1], 16;" :: "r"(dst), "l"(src) : "memory");
}
__device__ __forceinline__ void cp_commit() {
    asm volatile("cp.async.commit_group;" ::: "memory");
}
__device__ __forceinline__ void cp_wait1() {
    asm volatile("cp.async.wait_group 1;" ::: "memory");
}
__device__ __forceinline__ void cp_wait0() {
    asm volatile("cp.async.wait_group 0;" ::: "memory");
}

// split a float into bf16 hi + bf16 lo pair helpers
__device__ __forceinline__ void split2(float a, float b, __nv_bfloat162& hi, __nv_bfloat162& lo) {
    hi = __floats2bfloat162_rn(a, b);
    float2 f = __bfloat1622float2(hi);
    lo = __floats2bfloat162_rn(a - f.x, b - f.y);
}

// ---------------- graph/CSR build ----------------
__global__ void k_dinit(float* deg) { deg[threadIdx.x] = 1.f; }
__global__ void k_count(const int* __restrict__ ei, float* deg) {
    int e = blockIdx.x*blockDim.x + threadIdx.x;
    if (e < En) atomicAdd(&deg[ei[En + e]], 1.f);
}
__global__ void k_scan(const float* deg, float* dinv, int* rp, int* cur) {
    __shared__ int c[Pn];
    int p = threadIdx.x;
    dinv[p] = rsqrtf(deg[p]);
    c[p] = (int)deg[p];
    __syncthreads();
    if (p == 0) {
        int s = 0;
        for (int i = 0; i < Pn; i++) { rp[i] = s; cur[i] = s; s += c[i]; }
        rp[Pn] = s;
    }
}
__global__ void k_csrfill(const int* __restrict__ ei, const float* __restrict__ dinv,
                          int* cur, int* ci, float* wv) {
    int e = blockIdx.x*blockDim.x + threadIdx.x;
    if (e < En) {
        int s = ei[e], d = ei[En + e];
        int pos = atomicAdd(&cur[d], 1);
        ci[pos] = s; wv[pos] = dinv[s]*dinv[d];
    } else if (e < En + Pn) {
        int p = e - En;
        int pos = atomicAdd(&cur[p], 1);
        ci[pos] = p; wv[pos] = dinv[p]*dinv[p];
    }
}

// ---------------- weight pack: W[K,N] fp32 -> [N][3K] bf16 (hi|lo|hi) -------
__global__ void k_wprep3(const float* __restrict__ W, __nv_bfloat16* __restrict__ O,
                         int K, int N) {
    int idx = blockIdx.x*blockDim.x + threadIdx.x;
    if (idx >= K*N) return;
    int k = idx / N, n = idx - k*N;
    float a = W[idx];
    __nv_bfloat16 h = __float2bfloat16_rn(a);
    __nv_bfloat16 l = __float2bfloat16_rn(a - __bfloat162float(h));
    size_t base = (size_t)n*3*K;
    O[base + k]       = h;
    O[base + K + k]   = l;
    O[base + 2*K + k] = h;
}

// ---------------- input split: X[M,256] fp32 -> S[M,512] bf16 ---------------
__global__ void k_asplit(const float* __restrict__ X, __nv_bfloat16* __restrict__ S) {
    int idx = blockIdx.x*blockDim.x + threadIdx.x;  // one per 4 elems
    int row = idx >> 6;
    int g   = (idx & 63) * 4;
    float4 v = reinterpret_cast<const float4*>(X)[idx];
    __nv_bfloat162 h01, l01, h23, l23;
    split2(v.x, v.y, h01, l01);
    split2(v.z, v.w, h23, l23);
    __nv_bfloat16* hp = S + (size_t)row*512 + g;
    *reinterpret_cast<__nv_bfloat162*>(hp)     = h01;
    *reinterpret_cast<__nv_bfloat162*>(hp + 2) = h23;
    *reinterpret_cast<__nv_bfloat162*>(hp + 256)     = l01;
    *reinterpret_cast<__nv_bfloat162*>(hp + 256 + 2) = l23;
}

// ---------------- WMMA bf16 GEMM over augmented K ---------------------------
// C[M,Ntot] = A[M,K] @ B[K,Ntot]; A2: [M][2K] bf16 hi|lo; B3: [Ntot][3K] hi|lo|hi
// BM=BN=128, BK=32; 256 threads; warp grid 2(M)x4(N), warp tile 64x32.
#define ASTR 40                  // padded smem stride (bf16 elems)
#define TILE_B (128*ASTR*2)      // 10240 bytes per operand buffer
#define GEMM_SMEM (128*136*4)    // 69632 (stage dominates; operands overlap)

template<bool BIAS, bool RELU, bool WF32, bool WSPLIT>
__global__ void __launch_bounds__(256)
gemm_hmma(const __nv_bfloat16* __restrict__ A2, int lda,
          const __nv_bfloat16* __restrict__ B3, int ldb,
          const float* __restrict__ bias,
          float* __restrict__ C, __nv_bfloat16* __restrict__ Csp,
          int K, int Ntot)
{
    extern __shared__ __align__(128) char dsm[];
    const int tid = threadIdx.x;
    const int wid = tid >> 5;
    const int m0 = blockIdx.y * 128;
    const int n0 = blockIdx.x * 128;
    const int wm = wid & 1;      // 0..1
    const int wn = wid >> 1;     // 0..3

    uint32_t sbase = smem_u32(dsm);
    const int nc = K >> 5;       // fp32-K chunks
    const int NC = 3*nc;         // augmented chunks

    wmma::fragment<wmma::accumulator, 16,16,16, float> acc[4][2];
    #pragma unroll
    for (int i = 0; i < 4; i++)
        #pragma unroll
        for (int j = 0; j < 2; j++) wmma::fill_fragment(acc[i][j], 0.f);

    // chunk loader
    auto load_chunk = [&](int c, int buf) {
        int acol;
        if (c < nc)        acol = c << 5;
        else if (c < 2*nc) acol = (c - nc) << 5;
        else               acol = K + ((c - 2*nc) << 5);
        int bcol = c << 5;
        uint32_t da = sbase + buf*TILE_B;
        uint32_t db = sbase + 2*TILE_B + buf*TILE_B;
        #pragma unroll
        for (int r = 0; r < 2; r++) {
            int job = tid + r*256;
            int row = job >> 2, seg = (job & 3) * 8;
            cp_async16(da + row*(ASTR*2) + seg*2,
                       A2 + (size_t)(m0+row)*lda + acol + seg);
            cp_async16(db + row*(ASTR*2) + seg*2,
                       B3 + (size_t)(n0+row)*ldb + bcol + seg);
        }
        cp_commit();
    };

    load_chunk(0, 0);
    for (int c = 0; c < NC; c++) {
        int buf = c & 1;
        if (c + 1 < NC) { load_chunk(c+1, buf^1); cp_wait1(); }
        else            { cp_wait0(); }
        __syncthreads();

        const __nv_bfloat16* As = reinterpret_cast<const __nv_bfloat16*>(dsm + buf*TILE_B);
        const __nv_bfloat16* Bs = reinterpret_cast<const __nv_bfloat16*>(dsm + 2*TILE_B + buf*TILE_B);
        #pragma unroll
        for (int ks = 0; ks < 2; ks++) {
            wmma::fragment<wmma::matrix_a, 16,16,16, __nv_bfloat16, wmma::row_major> af[4];
            wmma::fragment<wmma::matrix_b, 16,16,16, __nv_bfloat16, wmma::col_major> bf[2];
            #pragma unroll
            for (int mt = 0; mt < 4; mt++)
                wmma::load_matrix_sync(af[mt], As + (wm*64 + mt*16)*ASTR + ks*16, ASTR);
            #pragma unroll
            for (int nt = 0; nt < 2; nt++)
                wmma::load_matrix_sync(bf[nt], Bs + (wn*32 + nt*16)*ASTR + ks*16, ASTR);
            #pragma unroll
            for (int mt = 0; mt < 4; mt++)
                #pragma unroll
                for (int nt = 0; nt < 2; nt++)
                    wmma::mma_sync(acc[mt][nt], af[mt], bf[nt], acc[mt][nt]);
        }
        __syncthreads();
    }

    // epilogue: stage to smem, then elementwise
    float* stage = reinterpret_cast<float*>(dsm);
    #pragma unroll
    for (int mt = 0; mt < 4; mt++)
        #pragma unroll
        for (int nt = 0; nt < 2; nt++)
            wmma::store_matrix_sync(stage + (wm*64 + mt*16)*136 + wn*32 + nt*16,
                                    acc[mt][nt], 136, wmma::mem_row_major);
    __syncthreads();

    int row = tid >> 1;
    int cb  = (tid & 1) * 64;
    const float* sr = stage + row*136 + cb;
    size_t crow = (size_t)(m0+row)*Ntot + n0 + cb;
    size_t shrow = (size_t)(m0+row)*(2*(size_t)Ntot) + n0 + cb;
    #pragma unroll
    for (int j = 0; j < 64; j += 4) {
        float4 v = *reinterpret_cast<const float4*>(sr + j);
        if (BIAS) {
            float4 b = *reinterpret_cast<const float4*>(bias + n0 + cb + j);
            v.x += b.x; v.y += b.y; v.z += b.z; v.w += b.w;
        }
        if (RELU) {
            v.x = fmaxf(v.x, 0.f); v.y = fmaxf(v.y, 0.f);
            v.z = fmaxf(v.z, 0.f); v.w = fmaxf(v.w, 0.f);
        }
        if (WF32) *reinterpret_cast<float4*>(C + crow + j) = v;
        if (WSPLIT) {
            __nv_bfloat162 h01, l01, h23, l23;
            split2(v.x, v.y, h01, l01);
            split2(v.z, v.w, h23, l23);
            __nv_bfloat16* hp = Csp + shrow + j;
            *reinterpret_cast<__nv_bfloat162*>(hp)     = h01;
            *reinterpret_cast<__nv_bfloat162*>(hp + 2) = h23;
            *reinterpret_cast<__nv_bfloat162*>(hp + Ntot)     = l01;
            *reinterpret_cast<__nv_bfloat162*>(hp + Ntot + 2) = l23;
        }
    }
}

// ---------------- sparse GCN aggregation (+bias +relu) ----------------------
// out split always written (width 512); optional fp32 out (width 256)
template<bool WF32>
__global__ void __launch_bounds__(256)
agg_csr(const float* __restrict__ xw, const int* __restrict__ rp,
        const int* __restrict__ ci, const float* __restrict__ wv,
        const float* __restrict__ bias, float* __restrict__ outf,
        __nv_bfloat16* __restrict__ sp)
{
    int warp = blockIdx.x*8 + (threadIdx.x >> 5);
    int lane = threadIdx.x & 31;
    int p = warp & 127;
    size_t gbase = (size_t)(warp & ~127) * Dn;

    float4 a0 = make_float4(0.f,0.f,0.f,0.f);
    float4 a1 = make_float4(0.f,0.f,0.f,0.f);
    int s0 = rp[p], s1 = rp[p+1];
    for (int e = s0; e < s1; e++) {
        int src = ci[e]; float w = wv[e];
        const float4* rowp = reinterpret_cast<const float4*>(xw + gbase + (size_t)src*Dn);
        float4 x0 = rowp[lane];
        float4 x1 = rowp[lane+32];
        a0.x = fmaf(w, x0.x, a0.x); a0.y = fmaf(w, x0.y, a0.y);
        a0.z = fmaf(w, x0.z, a0.z); a0.w = fmaf(w, x0.w, a0.w);
        a1.x = fmaf(w, x1.x, a1.x); a1.y = fmaf(w, x1.y, a1.y);
        a1.z = fmaf(w, x1.z, a1.z); a1.w = fmaf(w, x1.w, a1.w);
    }
    int c0 = lane*4;
    float4 b0 = *reinterpret_cast<const float4*>(bias + c0);
    float4 b1 = *reinterpret_cast<const float4*>(bias + c0 + 128);
    a0.x = fmaxf(a0.x + b0.x, 0.f); a0.y = fmaxf(a0.y + b0.y, 0.f);
    a0.z = fmaxf(a0.z + b0.z, 0.f); a0.w = fmaxf(a0.w + b0.w, 0.f);
    a1.x = fmaxf(a1.x + b1.x, 0.f); a1.y = fmaxf(a1.y + b1.y, 0.f);
    a1.z = fmaxf(a1.z + b1.z, 0.f); a1.w = fmaxf(a1.w + b1.w, 0.f);

    if (WF32) {
        float* dst = outf + (size_t)warp*Dn;
        *reinterpret_cast<float4*>(dst + c0)       = a0;
        *reinterpret_cast<float4*>(dst + c0 + 128) = a1;
    }
    __nv_bfloat16* sprow = sp + (size_t)warp*512;
    __nv_bfloat162 h01, l01, h23, l23;
    split2(a0.x, a0.y, h01, l01); split2(a0.z, a0.w, h23, l23);
    *reinterpret_cast<__nv_bfloat162*>(sprow + c0)     = h01;
    *reinterpret_cast<__nv_bfloat162*>(sprow + c0 + 2) = h23;
    *reinterpret_cast<__nv_bfloat162*>(sprow + 256 + c0)     = l01;
    *reinterpret_cast<__nv_bfloat162*>(sprow + 256 + c0 + 2) = l23;
    split2(a1.x, a1.y, h01, l01); split2(a1.z, a1.w, h23, l23);
    *reinterpret_cast<__nv_bfloat162*>(sprow + c0 + 128)     = h01;
    *reinterpret_cast<__nv_bfloat162*>(sprow + c0 + 130)     = h23;
    *reinterpret_cast<__nv_bfloat162*>(sprow + 256 + c0 + 128) = l01;
    *reinterpret_cast<__nv_bfloat162*>(sprow + 256 + c0 + 130) = l23;
}

// ---------------- attention: one CTA per (head, graph); split bf16 out ------
__global__ void __launch_bounds__(128)
attn_kernel(const float* __restrict__ q, const float* __restrict__ k,
            const float* __restrict__ v, __nv_bfloat16* __restrict__ sp)
{
    int head = blockIdx.x;
    int g    = blockIdx.y;
    int tid  = threadIdx.x;

    __shared__ float Ks[Pn][HDn];
    __shared__ float Vs[Pn][HDn];

    size_t rowbase = ((size_t)g*Pn + tid)*Dn + head*HDn;
    #pragma unroll
    for (int j = 0; j < HDn/4; j++) {
        reinterpret_cast<float4*>(Ks[tid])[j] = reinterpret_cast<const float4*>(k + rowbase)[j];
        reinterpret_cast<float4*>(Vs[tid])[j] = reinterpret_cast<const float4*>(v + rowbase)[j];
    }
    float qr[HDn];
    #pragma unroll
    for (int j = 0; j < HDn/4; j++) {
        float4 t4 = reinterpret_cast<const float4*>(q + rowbase)[j];
        qr[4*j+0] = t4.x; qr[4*j+1] = t4.y; qr[4*j+2] = t4.z; qr[4*j+3] = t4.w;
    }
    __syncthreads();

    const float scale = 0.17677669529663687f;   // 1/sqrt(32)
    float l = 0.f;
    float acc[HDn];
    #pragma unroll
    for (int d = 0; d < HDn; d++) acc[d] = 0.f;
    for (int j = 0; j < Pn; j++) {
        float s = 0.f;
        #pragma unroll
        for (int d = 0; d < HDn; d++) s = fmaf(qr[d], Ks[j][d], s);
        float e = __expf(s*scale);
        l += e;
        #pragma unroll
        for (int d = 0; d < HDn; d++) acc[d] = fmaf(e, Vs[j][d], acc[d]);
    }
    float inv = 1.f / l;
    __nv_bfloat16* sprow = sp + ((size_t)g*Pn + tid)*512 + head*HDn;
    #pragma unroll
    for (int j = 0; j < HDn; j += 4) {
        float a = acc[j]*inv, b = acc[j+1]*inv, c = acc[j+2]*inv, d = acc[j+3]*inv;
        __nv_bfloat162 h01, l01, h23, l23;
        split2(a, b, h01, l01);
        split2(c, d, h23, l23);
        *reinterpret_cast<__nv_bfloat162*>(sprow + j)     = h01;
        *reinterpret_cast<__nv_bfloat162*>(sprow + j + 2) = h23;
        *reinterpret_cast<__nv_bfloat162*>(sprow + 256 + j)     = l01;
        *reinterpret_cast<__nv_bfloat162*>(sprow + 256 + j + 2) = l23;
    }
}

// ---------------- LayerNorm(x + t)*g + b ; fp32 out + optional split --------
template<bool WSPLIT>
__global__ void __launch_bounds__(Dn)
ln_kernel(const float* __restrict__ x, const float* __restrict__ t,
          const float* __restrict__ gam, const float* __restrict__ bet,
          float* __restrict__ out, __nv_bfloat16* __restrict__ sp)
{
    int row = blockIdx.x;
    int f   = threadIdx.x;
    size_t idx = (size_t)row*Dn + f;
    float v = x[idx] + t[idx];

    __shared__ float sh[8];
    int lane = f & 31, w = f >> 5;

    float s = v;
    #pragma unroll
    for (int off = 16; off > 0; off >>= 1) s += __shfl_xor_sync(0xffffffffu, s, off);
    if (lane == 0) sh[w] = s;
    __syncthreads();
    float mean = 0.f;
    #pragma unroll
    for (int i = 0; i < 8; i++) mean += sh[i];
    mean *= (1.f/Dn);

    float d  = v - mean;
    float s2 = d*d;
    #pragma unroll
    for (int off = 16; off > 0; off >>= 1) s2 += __shfl_xor_sync(0xffffffffu, s2, off);
    __syncthreads();
    if (lane == 0) sh[w] = s2;
    __syncthreads();
    float var = 0.f;
    #pragma unroll
    for (int i = 0; i < 8; i++) var += sh[i];
    var *= (1.f/Dn);

    float r = rsqrtf(var + 1e-5f);
    float o = d*r*gam[f] + bet[f];
    out[idx] = o;
    if (WSPLIT) {
        __nv_bfloat16 h = __float2bfloat16_rn(o);
        __nv_bfloat16 l = __float2bfloat16_rn(o - __bfloat162float(h));
        sp[(size_t)row*512 + f]       = h;
        sp[(size_t)row*512 + 256 + f] = l;
    }
}

// ---------------------------------------------------------------------------
extern "C" void kernel_launch(void* const* d_in, const int* in_sizes, int n_in,
                              void* d_out, int out_size)
{
    const float* x    = (const float*)d_in[0];
    const int*   ei   = (const int*)  d_in[1];
    const float* c1W  = (const float*)d_in[6];
    const float* c1b  = (const float*)d_in[7];
    const float* c2W  = (const float*)d_in[8];
    const float* c2b  = (const float*)d_in[9];
    const float* WqA  = (const float*)d_in[10];
    const float* bqA  = (const float*)d_in[11];
    const float* WkA  = (const float*)d_in[12];
    const float* bkA  = (const float*)d_in[13];
    const float* WvA  = (const float*)d_in[14];
    const float* bvA  = (const float*)d_in[15];
    const float* WoA  = (const float*)d_in[16];
    const float* boA  = (const float*)d_in[17];
    const float* W1A  = (const float*)d_in[18];
    const float* b1A  = (const float*)d_in[19];
    const float* W2A  = (const float*)d_in[20];
    const float* b2A  = (const float*)d_in[21];
    const float* l1gA = (const float*)d_in[22];
    const float* l1bA = (const float*)d_in[23];
    const float* l2gA = (const float*)d_in[24];
    const float* l2bA = (const float*)d_in[25];
    float* out = (float*)d_out;

    float *h, *q, *k, *v, *degf, *dinv, *wv;
    __nv_bfloat16 *as1, *as2, *w3;
    int *rp, *cur, *ci;
    cudaGetSymbolAddress((void**)&h,    g_h);
    cudaGetSymbolAddress((void**)&q,    g_q);
    cudaGetSymbolAddress((void**)&k,    g_k);
    cudaGetSymbolAddress((void**)&v,    g_v);
    cudaGetSymbolAddress((void**)&as1,  g_as1);
    cudaGetSymbolAddress((void**)&as2,  g_as2);
    cudaGetSymbolAddress((void**)&w3,   g_w3);
    cudaGetSymbolAddress((void**)&degf, g_degf);
    cudaGetSymbolAddress((void**)&dinv, g_dinv);
    cudaGetSymbolAddress((void**)&rp,   g_rp);
    cudaGetSymbolAddress((void**)&cur,  g_cur);
    cudaGetSymbolAddress((void**)&ci,   g_ci);
    cudaGetSymbolAddress((void**)&wv,   g_wv);

    cudaFuncSetAttribute(gemm_hmma<false,false,true ,false>, cudaFuncAttributeMaxDynamicSharedMemorySize, GEMM_SMEM);
    cudaFuncSetAttribute(gemm_hmma<true ,false,true ,false>, cudaFuncAttributeMaxDynamicSharedMemorySize, GEMM_SMEM);
    cudaFuncSetAttribute(gemm_hmma<true ,true ,false,true >, cudaFuncAttributeMaxDynamicSharedMemorySize, GEMM_SMEM);

    // ---- CSR build ----
    k_dinit<<<1, Pn>>>(degf);
    k_count<<<(En+255)/256, 256>>>(ei, degf);
    k_scan <<<1, Pn>>>(degf, dinv, rp, cur);
    k_csrfill<<<(En+Pn+255)/256, 256>>>(ei, dinv, cur, ci, wv);

    // ---- weight pack (hi|lo|hi, [N][3K]) ----
    const size_t oC1 = 0, oC2 = W3_CONV;
    const size_t oL  = 2*W3_CONV;
    k_wprep3<<<(65536+255)/256, 256>>>(c1W, w3+oC1, Dn, Dn);
    k_wprep3<<<(65536+255)/256, 256>>>(c2W, w3+oC2, Dn, Dn);
    for (int l = 0; l < 2; l++) {
        size_t b = oL + (size_t)l*W3_LAYER;
        k_wprep3<<<(65536+255)/256, 256>>>(WqA + (size_t)l*65536,  w3+b,             Dn, Dn);
        k_wprep3<<<(65536+255)/256, 256>>>(WkA + (size_t)l*65536,  w3+b+W3_CONV,     Dn, Dn);
        k_wprep3<<<(65536+255)/256, 256>>>(WvA + (size_t)l*65536,  w3+b+2*W3_CONV,   Dn, Dn);
        k_wprep3<<<(65536+255)/256, 256>>>(WoA + (size_t)l*65536,  w3+b+3*W3_CONV,   Dn, Dn);
        k_wprep3<<<(262144+255)/256,256>>>(W1A + (size_t)l*262144, w3+b+4*W3_CONV,   Dn, DFn);
        k_wprep3<<<(262144+255)/256,256>>>(W2A + (size_t)l*262144, w3+b+4*W3_CONV+DFn*3*Dn, DFn, Dn);
    }

    dim3 gD(Dn/128,  Mn/128);   // (2, 512)
    dim3 gF(DFn/128, Mn/128);   // (8, 512)

    // ---- GCN ----
    k_asplit<<<(Mn*64)/256, 256>>>(x, as1);
    gemm_hmma<false,false,true,false><<<gD, 256, GEMM_SMEM>>>(as1, 512, w3+oC1, 768, nullptr, q, nullptr, Dn, Dn);
    agg_csr<false><<<Mn/8, 256>>>(q, rp, ci, wv, c1b, nullptr, as1);
    gemm_hmma<false,false,true,false><<<gD, 256, GEMM_SMEM>>>(as1, 512, w3+oC2, 768, nullptr, q, nullptr, Dn, Dn);
    agg_csr<true ><<<Mn/8, 256>>>(q, rp, ci, wv, c2b, h, as1);

    // ---- transformer layers ----
    for (int l = 0; l < 2; l++) {
        size_t b = oL + (size_t)l*W3_LAYER;
        const float* bq = bqA + (size_t)l*Dn;
        const float* bk = bkA + (size_t)l*Dn;
        const float* bv = bvA + (size_t)l*Dn;
        const float* bo = boA + (size_t)l*Dn;
        const float* b1 = b1A + (size_t)l*DFn;
        const float* b2 = b2A + (size_t)l*Dn;
        const float* l1g = l1gA + (size_t)l*Dn; const float* l1b = l1bA + (size_t)l*Dn;
        const float* l2g = l2gA + (size_t)l*Dn; const float* l2b = l2bA + (size_t)l*Dn;

        gemm_hmma<true,false,true,false><<<gD, 256, GEMM_SMEM>>>(as1, 512, w3+b,           768, bq, q, nullptr, Dn, Dn);
        gemm_hmma<true,false,true,false><<<gD, 256, GEMM_SMEM>>>(as1, 512, w3+b+W3_CONV,   768, bk, k, nullptr, Dn, Dn);
        gemm_hmma<true,false,true,false><<<gD, 256, GEMM_SMEM>>>(as1, 512, w3+b+2*W3_CONV, 768, bv, v, nullptr, Dn, Dn);

        attn_kernel<<<dim3(Hn, Gn), 128>>>(q, k, v, as1);

        gemm_hmma<true,false,true,false><<<gD, 256, GEMM_SMEM>>>(as1, 512, w3+b+3*W3_CONV, 768, bo, q, nullptr, Dn, Dn);
        ln_kernel<true><<<Mn, Dn>>>(h, q, l1g, l1b, h, as1);

        gemm_hmma<true,true,false,true><<<gF, 256, GEMM_SMEM>>>(as1, 512, w3+b+4*W3_CONV, 768, b1, nullptr, as2, Dn, DFn);
        gemm_hmma<true,false,true,false><<<gD, 256, GEMM_SMEM>>>(as2, 2048, w3+b+4*W3_CONV+DFn*3*Dn, 3072, b2, q, nullptr, DFn, Dn);

        if (l == 0) ln_kernel<true ><<<Mn, Dn>>>(h, q, l2g, l2b, h, as1);
        else        ln_kernel<false><<<Mn, Dn>>>(h, q, l2g, l2b, out, nullptr);
    }
}